// round 14
// baseline (speedup 1.0000x reference)
#include <cuda_runtime.h>
#include <cstdint>

#define N_ 4096
#define D_ 5000
#define H_ 512
#define C_ 4
#define L_ 8
#define BK 16
#define ST 68
#define SAT 36
#define SP 20
#define CHUNK (1024 * 512)

// ---------------- scratch: 56 MiB ----------------
__device__ float g_xhat[N_ * H_];   // E(x), original row order
__device__ float g_xr[N_ * H_];     // compact order
__device__ float g_xz[N_ * H_];     // compact order
__device__ float g_xh[N_ * H_];     // compact order
__device__ float g_hc[N_ * H_];     // hidden state, COMPACT (level-sorted) order
__device__ float g_hs[N_ * H_];     // per-level hs (level-local rows)
__device__ float g_rhs[N_ * H_];    // c0..c3: split-K partials; then c0 rhs, c1 z
__device__ int   g_rows[N_];        // compact -> original, sorted within level
__device__ int   g_off[16];

// ---------------- level bucketing (deterministic, sorted) ----------------
__global__ void lvl_init_k() {
    int t = threadIdx.x;
    if (t < 16) g_off[t] = 0;
}
__global__ void lvl_hist_k(const int* __restrict__ level) {
    int i = blockIdx.x * blockDim.x + threadIdx.x;
    if (i < N_) atomicAdd(&g_off[level[i] + 1], 1);
}
__global__ void lvl_scan_k() {
    if (threadIdx.x == 0)
        for (int j = 1; j <= L_; j++) g_off[j] += g_off[j - 1];
}
__global__ void lvl_rank_k(const int* __restrict__ level) {
    __shared__ int slv[N_];
    for (int i = threadIdx.x; i < N_; i += blockDim.x) slv[i] = level[i];
    __syncthreads();
    int i = blockIdx.x * blockDim.x + threadIdx.x;
    if (i < N_) {
        int l = slv[i];
        int r = 0;
        for (int j = 0; j < i; j++) r += (slv[j] == l) ? 1 : 0;
        g_rows[g_off[l] + r] = i;
    }
}

__device__ __forceinline__ float sigm_(float v) { return 1.f / (1.f + expf(-v)); }

// ---- level L-1 closed form (bitwise-exact vs GEMM path): hs == 0, rhs == 0
//      => h = sigm(xz) * tanh(xh)
__global__ void lvl7_k() {
    int o0 = g_off[L_ - 1];
    int M = g_off[L_] - o0;
    long idx = (long)blockIdx.x * 256 + threadIdx.x;
    int m = (int)(idx >> 9);
    if (m >= M) return;
    long cr = (long)(o0 + m) * H_ + (idx & 511);
    g_hc[cr] = sigm_(g_xz[cr]) * tanhf(g_xh[cr]);
}

// ================= 3xTF32 mma machinery (validated) =================
__device__ __forceinline__ uint32_t fu(float f) { return __float_as_uint(f); }
__device__ __forceinline__ void tf32split(float v, float& hi, float& lo) {
    uint32_t b;
    asm("cvt.rna.tf32.f32 %0, %1;" : "=r"(b) : "f"(v));
    hi = __uint_as_float(b);
    lo = v - hi;
}
__device__ __forceinline__ void mma8(float c[4], const uint32_t a[4],
                                     uint32_t b0, uint32_t b1) {
    asm volatile(
        "mma.sync.aligned.m16n8k8.row.col.f32.tf32.tf32.f32 "
        "{%0,%1,%2,%3}, {%4,%5,%6,%7}, {%8,%9}, {%0,%1,%2,%3};"
        : "+f"(c[0]), "+f"(c[1]), "+f"(c[2]), "+f"(c[3])
        : "r"(a[0]), "r"(a[1]), "r"(a[2]), "r"(a[3]), "r"(b0), "r"(b1));
}
__device__ __forceinline__ float4 ldraw(const float* __restrict__ src, long ld,
                                        int K, int k0, int r0) {
    int lr = threadIdx.x >> 2;
    int lc = (threadIdx.x & 3) << 2;
    int gk = k0 + lc;
    float4 v = make_float4(0.f, 0.f, 0.f, 0.f);
    if (gk < K) v = *(const float4*)(src + (long)(r0 + lr) * ld + gk);
    return v;
}
__device__ __forceinline__ float4 ldrawG(const float* __restrict__ src, long ld,
                                         int k0, int r0,
                                         const int* __restrict__ rows) {
    int lr = threadIdx.x >> 2;
    int lc = (threadIdx.x & 3) << 2;
    return *(const float4*)(src + (long)rows[r0 + lr] * ld + k0 + lc);
}
__device__ __forceinline__ void split_store(float (*sH)[SP], float (*sL)[SP], float4 v) {
    int lr = threadIdx.x >> 2;
    int lc = (threadIdx.x & 3) << 2;
    float h0, l0, h1, l1, h2, l2, h3, l3;
    tf32split(v.x, h0, l0); tf32split(v.y, h1, l1);
    tf32split(v.z, h2, l2); tf32split(v.w, h3, l3);
    *(float4*)&sH[lr][lc] = make_float4(h0, h1, h2, h3);
    *(float4*)&sL[lr][lc] = make_float4(l0, l1, l2, l3);
}
__device__ __forceinline__ void mma_tile(float acc[2][2][4],
                                         const float (*sAh)[SP], const float (*sAl)[SP],
                                         const float (*sBh)[SP], const float (*sBl)[SP],
                                         int wm, int wn, int g, int tg) {
#pragma unroll
    for (int kk = 0; kk < 16; kk += 8) {
        uint32_t ah[2][4], al[2][4];
#pragma unroll
        for (int mt = 0; mt < 2; mt++) {
            int r0 = wm + mt * 16 + g;
            ah[mt][0] = fu(sAh[r0][kk + tg]);     ah[mt][1] = fu(sAh[r0 + 8][kk + tg]);
            ah[mt][2] = fu(sAh[r0][kk + tg + 4]); ah[mt][3] = fu(sAh[r0 + 8][kk + tg + 4]);
            al[mt][0] = fu(sAl[r0][kk + tg]);     al[mt][1] = fu(sAl[r0 + 8][kk + tg]);
            al[mt][2] = fu(sAl[r0][kk + tg + 4]); al[mt][3] = fu(sAl[r0 + 8][kk + tg + 4]);
        }
#pragma unroll
        for (int nt = 0; nt < 2; nt++) {
            int c = wn + nt * 8 + g;
            uint32_t bh0 = fu(sBh[c][kk + tg]), bh1 = fu(sBh[c][kk + tg + 4]);
            uint32_t bl0 = fu(sBl[c][kk + tg]), bl1 = fu(sBl[c][kk + tg + 4]);
#pragma unroll
            for (int mt = 0; mt < 2; mt++) {
                mma8(acc[mt][nt], ah[mt], bh0, bh1);
                mma8(acc[mt][nt], al[mt], bh0, bh1);
                mma8(acc[mt][nt], ah[mt], bl0, bl1);
            }
        }
    }
}

// ---------------- x_hat = x @ E_w^T  (3xTF32, double-buffered) ----------------
__global__ __launch_bounds__(256) void mm_xhat(const float* __restrict__ x,
                                               const float* __restrict__ Ew) {
    __shared__ float sAh[2][64][SP], sAl[2][64][SP], sBh[2][64][SP], sBl[2][64][SP];
    int m0 = blockIdx.y * 64, n0 = blockIdx.x * 64;
    int wid = threadIdx.x >> 5, lane = threadIdx.x & 31;
    int g = lane >> 2, tg = lane & 3;
    int wm = (wid & 1) * 32, wn = (wid >> 1) * 16;
    float acc[2][2][4] = {};
    const int nsl = (D_ + BK - 1) / BK;
    float4 ra = ldraw(x, D_, D_, 0, m0);
    float4 rb = ldraw(Ew, D_, D_, 0, n0);
    split_store(sAh[0], sAl[0], ra);
    split_store(sBh[0], sBl[0], rb);
    __syncthreads();
    int cur = 0;
    for (int s = 0; s < nsl; s++) {
        if (s + 1 < nsl) {
            ra = ldraw(x, D_, D_, (s + 1) * BK, m0);
            rb = ldraw(Ew, D_, D_, (s + 1) * BK, n0);
        }
        mma_tile(acc, sAh[cur], sAl[cur], sBh[cur], sBl[cur], wm, wn, g, tg);
        if (s + 1 < nsl) {
            split_store(sAh[1 - cur], sAl[1 - cur], ra);
            split_store(sBh[1 - cur], sBl[1 - cur], rb);
        }
        __syncthreads();
        cur ^= 1;
    }
#pragma unroll
    for (int mt = 0; mt < 2; mt++)
#pragma unroll
        for (int nt = 0; nt < 2; nt++) {
            int r = m0 + wm + mt * 16 + g;
            int c = n0 + wn + nt * 8 + 2 * tg;
            g_xhat[(long)r * H_ + c]           = acc[mt][nt][0];
            g_xhat[(long)r * H_ + c + 1]       = acc[mt][nt][1];
            g_xhat[(long)(r + 8) * H_ + c]     = acc[mt][nt][2];
            g_xhat[(long)(r + 8) * H_ + c + 1] = acc[mt][nt][3];
        }
}

// ------ xr/xz/xh[compact] = xhat[rows] @ {Wr,Wz,Wh}^T  (3xTF32, shared A) -----
__global__ __launch_bounds__(256) void mm_xw(const float* __restrict__ Wr,
                                             const float* __restrict__ Wz,
                                             const float* __restrict__ Wh) {
    __shared__ float sAh[64][SP], sAl[64][SP];
    __shared__ float sBh[3][64][SP], sBl[3][64][SP];
    int m0 = blockIdx.y * 64, n0 = blockIdx.x * 64;
    int wid = threadIdx.x >> 5, lane = threadIdx.x & 31;
    int g = lane >> 2, tg = lane & 3;
    int wm = (wid & 1) * 32, wn = (wid >> 1) * 16;
    float acc[3][2][2][4] = {};
    for (int k0 = 0; k0 < H_; k0 += BK) {
        split_store(sAh, sAl, ldrawG(g_xhat, H_, k0, m0, g_rows));
        split_store(sBh[0], sBl[0], ldraw(Wr, H_, H_, k0, n0));
        split_store(sBh[1], sBl[1], ldraw(Wz, H_, H_, k0, n0));
        split_store(sBh[2], sBl[2], ldraw(Wh, H_, H_, k0, n0));
        __syncthreads();
#pragma unroll
        for (int w = 0; w < 3; w++)
            mma_tile(acc[w], sAh, sAl, sBh[w], sBl[w], wm, wn, g, tg);
        __syncthreads();
    }
    float* outs[3] = {g_xr, g_xz, g_xh};
#pragma unroll
    for (int w = 0; w < 3; w++)
#pragma unroll
        for (int mt = 0; mt < 2; mt++)
#pragma unroll
            for (int nt = 0; nt < 2; nt++) {
                int r = m0 + wm + mt * 16 + g;
                int c = n0 + wn + nt * 8 + 2 * tg;
                outs[w][(long)r * H_ + c]           = acc[w][mt][nt][0];
                outs[w][(long)r * H_ + c + 1]       = acc[w][mt][nt][1];
                outs[w][(long)(r + 8) * H_ + c]     = acc[w][mt][nt][2];
                outs[w][(long)(r + 8) * H_ + c + 1] = acc[w][mt][nt][3];
            }
}

// ================= fp32 tile slabs =================
__device__ __forceinline__ void sl44(float ac[4][4], const float (*sA)[ST],
                                     const float (*sB)[ST], int ty, int tx) {
#pragma unroll
    for (int k = 0; k < BK; k++) {
        float a[4], b[4];
        *(float4*)a = *(const float4*)&sA[k][ty * 4];
        *(float4*)b = *(const float4*)&sB[k][tx * 4];
#pragma unroll
        for (int i = 0; i < 4; i++)
#pragma unroll
            for (int j = 0; j < 4; j++) ac[i][j] = fmaf(a[i], b[j], ac[i][j]);
    }
}
// 4x4 dual-gate slab; A in small (32-row) tile
__device__ __forceinline__ void sl44d_g(float aR[4][4], float aZ[4][4],
                                        const float (*sA)[SAT], const float (*sB1)[ST],
                                        const float (*sB2)[ST], int ty, int tx) {
#pragma unroll
    for (int k = 0; k < BK; k++) {
        float a[4], b1[4], b2[4];
        *(float4*)a  = *(const float4*)&sA[k][ty * 4];
        *(float4*)b1 = *(const float4*)&sB1[k][tx * 4];
        *(float4*)b2 = *(const float4*)&sB2[k][tx * 4];
#pragma unroll
        for (int i = 0; i < 4; i++)
#pragma unroll
            for (int j = 0; j < 4; j++) {
                aR[i][j] = fmaf(a[i], b1[j], aR[i][j]);
                aZ[i][j] = fmaf(a[i], b2[j], aZ[i][j]);
            }
    }
}
__device__ __forceinline__ void sl44_g(float ac[4][4], const float (*sA)[SAT],
                                       const float (*sB)[ST], int ty, int tx) {
#pragma unroll
    for (int k = 0; k < BK; k++) {
        float a[4], b[4];
        *(float4*)a = *(const float4*)&sA[k][ty * 4];
        *(float4*)b = *(const float4*)&sB[k][tx * 4];
#pragma unroll
        for (int i = 0; i < 4; i++)
#pragma unroll
            for (int j = 0; j < 4; j++) ac[i][j] = fmaf(a[i], b[j], ac[i][j]);
    }
}

// ---- hs partials (fp32, exact column-skip): adj[rows_j, cols_act] @ hc ------
// K over compact rows [off[lvl+1], N). split-K = 4 via blockIdx.z.
__global__ __launch_bounds__(256) void mm_hs(const float* __restrict__ adj, int lvl) {
    int o0 = g_off[lvl], o1 = g_off[lvl + 1];
    int M = o1 - o0;
    int Ktot = N_ - o1;
    int m0 = blockIdx.y * 64;
    if (m0 >= M) return;
    const int* rows = g_rows + o0;
    const int* cols = g_rows + o1;
    int n0 = blockIdx.x * 64;
    int kchunk = ((Ktot + 63) >> 6) << 4;
    int kbase = blockIdx.z * kchunk;
    int kend = min(kbase + kchunk, Ktot);
    int nsl = (kend > kbase) ? ((kend - kbase + 15) >> 4) : 0;

    int ty = threadIdx.x >> 4, tx = threadIdx.x & 15;
    float ac[4][4] = {};
    if (nsl > 0) {
        __shared__ float sA[2][BK][ST], sB[2][BK][ST];
        int alr = threadIdx.x >> 2;
        int alc = (threadIdx.x & 3) << 2;
        int gm = m0 + alr;
        long arow = (gm < M) ? (long)rows[gm] * N_ : -1;
        int bkk = threadIdx.x >> 4;
        int bc  = (threadIdx.x & 15) << 2;
        float va[4]; float4 vb;
        {
#pragma unroll
            for (int t = 0; t < 4; t++) {
                int k = kbase + alc + t;
                va[t] = (arow >= 0 && k < kend) ? adj[arow + cols[k]] : 0.f;
            }
            int kb = kbase + bkk;
            vb = (kb < kend) ? *(const float4*)(g_hc + (long)(o1 + kb) * H_ + n0 + bc)
                             : make_float4(0.f, 0.f, 0.f, 0.f);
        }
        sA[0][alc + 0][alr] = va[0]; sA[0][alc + 1][alr] = va[1];
        sA[0][alc + 2][alr] = va[2]; sA[0][alc + 3][alr] = va[3];
        *(float4*)&sB[0][bkk][bc] = vb;
        __syncthreads();
        int cur = 0;
        for (int sl = 0; sl < nsl; sl++) {
            if (sl + 1 < nsl) {
                int k0 = kbase + (sl + 1) * BK;
#pragma unroll
                for (int t = 0; t < 4; t++) {
                    int k = k0 + alc + t;
                    va[t] = (arow >= 0 && k < kend) ? adj[arow + cols[k]] : 0.f;
                }
                int kb = k0 + bkk;
                vb = (kb < kend) ? *(const float4*)(g_hc + (long)(o1 + kb) * H_ + n0 + bc)
                                 : make_float4(0.f, 0.f, 0.f, 0.f);
            }
            sl44(ac, sA[cur], sB[cur], ty, tx);
            if (sl + 1 < nsl) {
                sA[1 - cur][alc + 0][alr] = va[0]; sA[1 - cur][alc + 1][alr] = va[1];
                sA[1 - cur][alc + 2][alr] = va[2]; sA[1 - cur][alc + 3][alr] = va[3];
                *(float4*)&sB[1 - cur][bkk][bc] = vb;
            }
            __syncthreads();
            cur ^= 1;
        }
    }
    float* P = g_rhs + (long)blockIdx.z * CHUNK;
#pragma unroll
    for (int i = 0; i < 4; i++) {
        int m = m0 + ty * 4 + i;
        if (m >= M) continue;
        *(float4*)&P[(long)m * H_ + n0 + tx * 4] = *(float4*)&ac[i][0];
    }
}
__global__ void reduce_hs_k(int lvl) {
    int M = g_off[lvl + 1] - g_off[lvl];
    long idx = (long)blockIdx.x * 256 + threadIdx.x;
    int m = (int)(idx >> 9);
    if (m >= M) return;
    g_hs[idx] = g_rhs[idx] + g_rhs[idx + CHUNK] +
                g_rhs[idx + 2L * CHUNK] + g_rhs[idx + 3L * CHUNK];
}

// ---- r & z gates: fp32, BM=32/BN=64, 128 threads, 4x4/thread ---------------
// Same k-accumulation order per output element as before -> bitwise identical.
__global__ __launch_bounds__(128) void mm_rz(const float* __restrict__ Ur,
                                             const float* __restrict__ Uz, int lvl) {
    int o0 = g_off[lvl];
    int M = g_off[lvl + 1] - o0;
    int m0 = blockIdx.y * 32;
    if (m0 >= M) return;
    int n0 = blockIdx.x * 64;
    __shared__ float sA[2][BK][SAT], sB1[2][BK][ST], sB2[2][BK][ST];
    int alr = threadIdx.x >> 2;          // A row 0..31
    int alc = (threadIdx.x & 3) << 2;    // A k 0,4,8,12 (float4)
    int blr = threadIdx.x >> 1;          // B row 0..63
    int bk  = (threadIdx.x & 1) << 3;    // B k 0 or 8 (2x float4)
    int ty = threadIdx.x >> 4, tx = threadIdx.x & 15;
    float aR[4][4] = {}, aZ[4][4] = {};
    const int nsl = H_ / BK;
    float4 va, v1a, v1b, v2a, v2b;
    auto stage = [&](int buf) {
        sA[buf][alc + 0][alr] = va.x; sA[buf][alc + 1][alr] = va.y;
        sA[buf][alc + 2][alr] = va.z; sA[buf][alc + 3][alr] = va.w;
        sB1[buf][bk + 0][blr] = v1a.x; sB1[buf][bk + 1][blr] = v1a.y;
        sB1[buf][bk + 2][blr] = v1a.z; sB1[buf][bk + 3][blr] = v1a.w;
        sB1[buf][bk + 4][blr] = v1b.x; sB1[buf][bk + 5][blr] = v1b.y;
        sB1[buf][bk + 6][blr] = v1b.z; sB1[buf][bk + 7][blr] = v1b.w;
        sB2[buf][bk + 0][blr] = v2a.x; sB2[buf][bk + 1][blr] = v2a.y;
        sB2[buf][bk + 2][blr] = v2a.z; sB2[buf][bk + 3][blr] = v2a.w;
        sB2[buf][bk + 4][blr] = v2b.x; sB2[buf][bk + 5][blr] = v2b.y;
        sB2[buf][bk + 6][blr] = v2b.z; sB2[buf][bk + 7][blr] = v2b.w;
    };
    auto load = [&](int k0) {
        va  = *(const float4*)(g_hs + (long)(m0 + alr) * H_ + k0 + alc);
        v1a = *(const float4*)(Ur + (long)(n0 + blr) * H_ + k0 + bk);
        v1b = *(const float4*)(Ur + (long)(n0 + blr) * H_ + k0 + bk + 4);
        v2a = *(const float4*)(Uz + (long)(n0 + blr) * H_ + k0 + bk);
        v2b = *(const float4*)(Uz + (long)(n0 + blr) * H_ + k0 + bk + 4);
    };
    load(0);
    stage(0);
    __syncthreads();
    int cur = 0;
    for (int sl = 0; sl < nsl; sl++) {
        if (sl + 1 < nsl) load((sl + 1) * BK);
        sl44d_g(aR, aZ, sA[cur], sB1[cur], sB2[cur], ty, tx);
        if (sl + 1 < nsl) stage(1 - cur);
        __syncthreads();
        cur ^= 1;
    }
#pragma unroll
    for (int i = 0; i < 4; i++) {
        int m = m0 + ty * 4 + i;
        if (m >= M) continue;
        long cr = (long)(o0 + m) * H_;
        long lm = (long)m * H_;
#pragma unroll
        for (int j = 0; j < 4; j++) {
            int n = n0 + tx * 4 + j;
            float r = sigm_(g_xr[cr + n] + aR[i][j]);
            float z = sigm_(g_xz[cr + n] + aZ[i][j]);
            g_rhs[lm + n] = g_hs[lm + n] * r;
            g_rhs[CHUNK + lm + n] = z;
        }
    }
}

// ---- h-tilde + GRU combine: fp32, BM=32/BN=64, 128 threads, 4x4/thread ------
__global__ __launch_bounds__(128) void mm_h(const float* __restrict__ Uh, int lvl) {
    int o0 = g_off[lvl];
    int M = g_off[lvl + 1] - o0;
    int m0 = blockIdx.y * 32;
    if (m0 >= M) return;
    int n0 = blockIdx.x * 64;
    __shared__ float sA[2][BK][SAT], sB[2][BK][ST];
    int alr = threadIdx.x >> 2;
    int alc = (threadIdx.x & 3) << 2;
    int blr = threadIdx.x >> 1;
    int bk  = (threadIdx.x & 1) << 3;
    int ty = threadIdx.x >> 4, tx = threadIdx.x & 15;
    float ac[4][4] = {};
    const int nsl = H_ / BK;
    float4 va, vba, vbb;
    auto stage = [&](int buf) {
        sA[buf][alc + 0][alr] = va.x; sA[buf][alc + 1][alr] = va.y;
        sA[buf][alc + 2][alr] = va.z; sA[buf][alc + 3][alr] = va.w;
        sB[buf][bk + 0][blr] = vba.x; sB[buf][bk + 1][blr] = vba.y;
        sB[buf][bk + 2][blr] = vba.z; sB[buf][bk + 3][blr] = vba.w;
        sB[buf][bk + 4][blr] = vbb.x; sB[buf][bk + 5][blr] = vbb.y;
        sB[buf][bk + 6][blr] = vbb.z; sB[buf][bk + 7][blr] = vbb.w;
    };
    auto load = [&](int k0) {
        va  = *(const float4*)(g_rhs + (long)(m0 + alr) * H_ + k0 + alc);
        vba = *(const float4*)(Uh + (long)(n0 + blr) * H_ + k0 + bk);
        vbb = *(const float4*)(Uh + (long)(n0 + blr) * H_ + k0 + bk + 4);
    };
    load(0);
    stage(0);
    __syncthreads();
    int cur = 0;
    for (int sl = 0; sl < nsl; sl++) {
        if (sl + 1 < nsl) load((sl + 1) * BK);
        sl44_g(ac, sA[cur], sB[cur], ty, tx);
        if (sl + 1 < nsl) stage(1 - cur);
        __syncthreads();
        cur ^= 1;
    }
#pragma unroll
    for (int i = 0; i < 4; i++) {
        int m = m0 + ty * 4 + i;
        if (m >= M) continue;
        long cr = (long)(o0 + m) * H_;
        long lm = (long)m * H_;
#pragma unroll
        for (int j = 0; j < 4; j++) {
            int n = n0 + tx * 4 + j;
            float hh = tanhf(g_xh[cr + n] + ac[i][j]);
            float z  = g_rhs[CHUNK + lm + n];
            float hs = g_hs[lm + n];
            g_hc[cr + n] = (1.f - z) * hs + z * hh;
        }
    }
}

// ---------------- decoder (compact -> original) ----------------
__global__ void decoder_k(const float* __restrict__ dw,
                          const float* __restrict__ db,
                          float* __restrict__ out) {
    int c = blockIdx.x;
    int tid = threadIdx.x;
    const float* hr = g_hc + (long)c * H_;
    float a0 = 0.f, a1 = 0.f, a2 = 0.f, a3 = 0.f;
    for (int k = tid; k < H_; k += 128) {
        float hv = hr[k];
        a0 = fmaf(hv, dw[0 * H_ + k], a0);
        a1 = fmaf(hv, dw[1 * H_ + k], a1);
        a2 = fmaf(hv, dw[2 * H_ + k], a2);
        a3 = fmaf(hv, dw[3 * H_ + k], a3);
    }
#pragma unroll
    for (int o = 16; o > 0; o >>= 1) {
        a0 += __shfl_down_sync(0xFFFFFFFFu, a0, o);
        a1 += __shfl_down_sync(0xFFFFFFFFu, a1, o);
        a2 += __shfl_down_sync(0xFFFFFFFFu, a2, o);
        a3 += __shfl_down_sync(0xFFFFFFFFu, a3, o);
    }
    __shared__ float s[4][4];
    int w = tid >> 5, l = tid & 31;
    if (l == 0) { s[w][0] = a0; s[w][1] = a1; s[w][2] = a2; s[w][3] = a3; }
    __syncthreads();
    if (tid < C_) {
        int orig = g_rows[c];
        out[(long)orig * C_ + tid] = s[0][tid] + s[1][tid] + s[2][tid] + s[3][tid] + db[tid];
    }
}

// ---------------- static-init preload ----------------
namespace {
struct Preload {
    Preload() {
        cudaSetDevice(0);
        void* p = nullptr;
        cudaGetSymbolAddress(&p, g_hc);
        cudaFuncAttributes at;
        cudaFuncGetAttributes(&at, lvl_init_k);
        cudaFuncGetAttributes(&at, lvl_hist_k);
        cudaFuncGetAttributes(&at, lvl_scan_k);
        cudaFuncGetAttributes(&at, lvl_rank_k);
        cudaFuncGetAttributes(&at, lvl7_k);
        cudaFuncGetAttributes(&at, mm_xhat);
        cudaFuncGetAttributes(&at, mm_xw);
        cudaFuncGetAttributes(&at, mm_hs);
        cudaFuncGetAttributes(&at, reduce_hs_k);
        cudaFuncGetAttributes(&at, mm_rz);
        cudaFuncGetAttributes(&at, mm_h);
        cudaFuncGetAttributes(&at, decoder_k);
        lvl_init_k<<<1, 32>>>();
        lvl_scan_k<<<1, 32>>>();
        cudaDeviceSynchronize();
        cudaGetLastError();
    }
};
Preload preload_;
}

// ---------------- launch ----------------
extern "C" void kernel_launch(void* const* d_in, const int* in_sizes, int n_in,
                              void* d_out, int out_size) {
    const float* x     = (const float*)d_in[0];
    const float* adj   = (const float*)d_in[1];
    const int*   level = (const int*)  d_in[2];
    const float* E_w   = (const float*)d_in[3];
    const float* Wr    = (const float*)d_in[4];
    const float* Wz    = (const float*)d_in[5];
    const float* Ur    = (const float*)d_in[6];
    const float* Uz    = (const float*)d_in[7];
    const float* Wh    = (const float*)d_in[8];
    const float* Uh    = (const float*)d_in[9];
    const float* dec_w = (const float*)d_in[10];
    const float* dec_b = (const float*)d_in[11];
    float* out = (float*)d_out;
    (void)in_sizes; (void)n_in; (void)out_size;

    lvl_init_k<<<1, 32>>>();
    lvl_hist_k<<<(N_ + 255) / 256, 256>>>(level);
    lvl_scan_k<<<1, 32>>>();
    lvl_rank_k<<<N_ / 256, 256>>>(level);

    mm_xhat<<<dim3(H_ / 64, N_ / 64), 256>>>(x, E_w);
    mm_xw<<<dim3(H_ / 64, N_ / 64), 256>>>(Wr, Wz, Wh);

    const int RB = CHUNK / 256;
    dim3 gGate(H_ / 64, 32);   // BM=32, covers M <= 1024
    for (int j = L_ - 1; j >= 0; j--) {
        if (j == L_ - 1) {
            lvl7_k<<<RB, 256>>>();   // closed form (bitwise-exact): h = sig(xz)*tanh(xh)
        } else {
            mm_hs<<<dim3(8, 16, 4), 256>>>(adj, j);
            reduce_hs_k<<<RB, 256>>>(j);
            mm_rz<<<gGate, 128>>>(Ur, Uz, j);
            mm_h<<<gGate, 128>>>(Uh, j);
        }
    }

    decoder_k<<<N_, 128>>>(dec_w, dec_b, out);
}

// round 15
// speedup vs baseline: 1.1302x; 1.1302x over previous
#include <cuda_runtime.h>
#include <cstdint>

#define N_ 4096
#define D_ 5000
#define H_ 512
#define C_ 4
#define L_ 8
#define BK 16
#define ST 68
#define SAT 36
#define SP 20
#define CHUNK (1024 * 512)

// ---------------- scratch: 56 MiB total ----------------
// g_xhat: xhat (8 MiB) before the level loop; adjP (packed adj tile, <=14 MiB)
// during the loop (xhat is dead after mm_xw).
__device__ float g_xhat[N_ * H_ + 3 * CHUNK];   // 14 MiB
__device__ float g_xr[N_ * H_];                 // 8 MiB, compact order
__device__ float g_xz[N_ * H_];                 // 8 MiB
__device__ float g_xh[N_ * H_];                 // 8 MiB
__device__ float g_hc[N_ * H_];                 // 8 MiB, hidden state (compact)
__device__ float g_hs[CHUNK];                   // 2 MiB, per-level hs (M<=1024)
__device__ float g_rhs[N_ * H_];                // 8 MiB: c0..c3 partials; c0 rhs, c1 z
__device__ int   g_rows[N_];
__device__ int   g_off[16];

// ---------------- level bucketing (deterministic, sorted) ----------------
__global__ void lvl_init_k() {
    int t = threadIdx.x;
    if (t < 16) g_off[t] = 0;
}
__global__ void lvl_hist_k(const int* __restrict__ level) {
    int i = blockIdx.x * blockDim.x + threadIdx.x;
    if (i < N_) atomicAdd(&g_off[level[i] + 1], 1);
}
__global__ void lvl_scan_k() {
    if (threadIdx.x == 0)
        for (int j = 1; j <= L_; j++) g_off[j] += g_off[j - 1];
}
__global__ void lvl_rank_k(const int* __restrict__ level) {
    __shared__ int slv[N_];
    for (int i = threadIdx.x; i < N_; i += blockDim.x) slv[i] = level[i];
    __syncthreads();
    int i = blockIdx.x * blockDim.x + threadIdx.x;
    if (i < N_) {
        int l = slv[i];
        int r = 0;
        for (int j = 0; j < i; j++) r += (slv[j] == l) ? 1 : 0;
        g_rows[g_off[l] + r] = i;
    }
}

__device__ __forceinline__ float sigm_(float v) { return 1.f / (1.f + expf(-v)); }

// ---- level L-1 closed form (bitwise-exact): hs == 0 => h = sigm(xz)*tanh(xh)
__global__ void lvl7_k() {
    int o0 = g_off[L_ - 1];
    int M = g_off[L_] - o0;
    long idx = (long)blockIdx.x * 256 + threadIdx.x;
    int m = (int)(idx >> 9);
    if (m >= M) return;
    long cr = (long)(o0 + m) * H_ + (idx & 511);
    g_hc[cr] = sigm_(g_xz[cr]) * tanhf(g_xh[cr]);
}

// ---- pack adj gather into dense adjP[m][Kpad] (coalesced writes) ----------
// adjP[m*Kpad + k] = adj[rows[m]][cols[k]] for k < Ktot, 0 in pad.
__global__ void pack_adj_k(const float* __restrict__ adj, int lvl) {
    int o0 = g_off[lvl], o1 = g_off[lvl + 1];
    int M = o1 - o0;
    int Ktot = N_ - o1;
    int Kpad = (Ktot + 63) & ~63;
    const int* rows = g_rows + o0;
    const int* cols = g_rows + o1;
    long total = (long)M * Kpad;
    for (long idx = (long)blockIdx.x * blockDim.x + threadIdx.x; idx < total;
         idx += (long)gridDim.x * blockDim.x) {
        int m = (int)(idx / Kpad);
        int k = (int)(idx - (long)m * Kpad);
        g_xhat[idx] = (k < Ktot) ? adj[(long)rows[m] * N_ + cols[k]] : 0.f;
    }
}

// ================= 3xTF32 mma machinery (validated) =================
__device__ __forceinline__ uint32_t fu(float f) { return __float_as_uint(f); }
__device__ __forceinline__ void tf32split(float v, float& hi, float& lo) {
    uint32_t b;
    asm("cvt.rna.tf32.f32 %0, %1;" : "=r"(b) : "f"(v));
    hi = __uint_as_float(b);
    lo = v - hi;
}
__device__ __forceinline__ void mma8(float c[4], const uint32_t a[4],
                                     uint32_t b0, uint32_t b1) {
    asm volatile(
        "mma.sync.aligned.m16n8k8.row.col.f32.tf32.tf32.f32 "
        "{%0,%1,%2,%3}, {%4,%5,%6,%7}, {%8,%9}, {%0,%1,%2,%3};"
        : "+f"(c[0]), "+f"(c[1]), "+f"(c[2]), "+f"(c[3])
        : "r"(a[0]), "r"(a[1]), "r"(a[2]), "r"(a[3]), "r"(b0), "r"(b1));
}
__device__ __forceinline__ float4 ldraw(const float* __restrict__ src, long ld,
                                        int K, int k0, int r0) {
    int lr = threadIdx.x >> 2;
    int lc = (threadIdx.x & 3) << 2;
    int gk = k0 + lc;
    float4 v = make_float4(0.f, 0.f, 0.f, 0.f);
    if (gk < K) v = *(const float4*)(src + (long)(r0 + lr) * ld + gk);
    return v;
}
__device__ __forceinline__ float4 ldrawG(const float* __restrict__ src, long ld,
                                         int k0, int r0,
                                         const int* __restrict__ rows) {
    int lr = threadIdx.x >> 2;
    int lc = (threadIdx.x & 3) << 2;
    return *(const float4*)(src + (long)rows[r0 + lr] * ld + k0 + lc);
}
__device__ __forceinline__ void split_store(float (*sH)[SP], float (*sL)[SP], float4 v) {
    int lr = threadIdx.x >> 2;
    int lc = (threadIdx.x & 3) << 2;
    float h0, l0, h1, l1, h2, l2, h3, l3;
    tf32split(v.x, h0, l0); tf32split(v.y, h1, l1);
    tf32split(v.z, h2, l2); tf32split(v.w, h3, l3);
    *(float4*)&sH[lr][lc] = make_float4(h0, h1, h2, h3);
    *(float4*)&sL[lr][lc] = make_float4(l0, l1, l2, l3);
}
__device__ __forceinline__ void mma_tile(float acc[2][2][4],
                                         const float (*sAh)[SP], const float (*sAl)[SP],
                                         const float (*sBh)[SP], const float (*sBl)[SP],
                                         int wm, int wn, int g, int tg) {
#pragma unroll
    for (int kk = 0; kk < 16; kk += 8) {
        uint32_t ah[2][4], al[2][4];
#pragma unroll
        for (int mt = 0; mt < 2; mt++) {
            int r0 = wm + mt * 16 + g;
            ah[mt][0] = fu(sAh[r0][kk + tg]);     ah[mt][1] = fu(sAh[r0 + 8][kk + tg]);
            ah[mt][2] = fu(sAh[r0][kk + tg + 4]); ah[mt][3] = fu(sAh[r0 + 8][kk + tg + 4]);
            al[mt][0] = fu(sAl[r0][kk + tg]);     al[mt][1] = fu(sAl[r0 + 8][kk + tg]);
            al[mt][2] = fu(sAl[r0][kk + tg + 4]); al[mt][3] = fu(sAl[r0 + 8][kk + tg + 4]);
        }
#pragma unroll
        for (int nt = 0; nt < 2; nt++) {
            int c = wn + nt * 8 + g;
            uint32_t bh0 = fu(sBh[c][kk + tg]), bh1 = fu(sBh[c][kk + tg + 4]);
            uint32_t bl0 = fu(sBl[c][kk + tg]), bl1 = fu(sBl[c][kk + tg + 4]);
#pragma unroll
            for (int mt = 0; mt < 2; mt++) {
                mma8(acc[mt][nt], ah[mt], bh0, bh1);
                mma8(acc[mt][nt], al[mt], bh0, bh1);
                mma8(acc[mt][nt], ah[mt], bl0, bl1);
            }
        }
    }
}

// ---------------- x_hat = x @ E_w^T  (3xTF32, double-buffered) ----------------
__global__ __launch_bounds__(256) void mm_xhat(const float* __restrict__ x,
                                               const float* __restrict__ Ew) {
    __shared__ float sAh[2][64][SP], sAl[2][64][SP], sBh[2][64][SP], sBl[2][64][SP];
    int m0 = blockIdx.y * 64, n0 = blockIdx.x * 64;
    int wid = threadIdx.x >> 5, lane = threadIdx.x & 31;
    int g = lane >> 2, tg = lane & 3;
    int wm = (wid & 1) * 32, wn = (wid >> 1) * 16;
    float acc[2][2][4] = {};
    const int nsl = (D_ + BK - 1) / BK;
    float4 ra = ldraw(x, D_, D_, 0, m0);
    float4 rb = ldraw(Ew, D_, D_, 0, n0);
    split_store(sAh[0], sAl[0], ra);
    split_store(sBh[0], sBl[0], rb);
    __syncthreads();
    int cur = 0;
    for (int s = 0; s < nsl; s++) {
        if (s + 1 < nsl) {
            ra = ldraw(x, D_, D_, (s + 1) * BK, m0);
            rb = ldraw(Ew, D_, D_, (s + 1) * BK, n0);
        }
        mma_tile(acc, sAh[cur], sAl[cur], sBh[cur], sBl[cur], wm, wn, g, tg);
        if (s + 1 < nsl) {
            split_store(sAh[1 - cur], sAl[1 - cur], ra);
            split_store(sBh[1 - cur], sBl[1 - cur], rb);
        }
        __syncthreads();
        cur ^= 1;
    }
#pragma unroll
    for (int mt = 0; mt < 2; mt++)
#pragma unroll
        for (int nt = 0; nt < 2; nt++) {
            int r = m0 + wm + mt * 16 + g;
            int c = n0 + wn + nt * 8 + 2 * tg;
            g_xhat[(long)r * H_ + c]           = acc[mt][nt][0];
            g_xhat[(long)r * H_ + c + 1]       = acc[mt][nt][1];
            g_xhat[(long)(r + 8) * H_ + c]     = acc[mt][nt][2];
            g_xhat[(long)(r + 8) * H_ + c + 1] = acc[mt][nt][3];
        }
}

// ------ xr/xz/xh[compact] = xhat[rows] @ {Wr,Wz,Wh}^T  (3xTF32, shared A) -----
__global__ __launch_bounds__(256) void mm_xw(const float* __restrict__ Wr,
                                             const float* __restrict__ Wz,
                                             const float* __restrict__ Wh) {
    __shared__ float sAh[64][SP], sAl[64][SP];
    __shared__ float sBh[3][64][SP], sBl[3][64][SP];
    int m0 = blockIdx.y * 64, n0 = blockIdx.x * 64;
    int wid = threadIdx.x >> 5, lane = threadIdx.x & 31;
    int g = lane >> 2, tg = lane & 3;
    int wm = (wid & 1) * 32, wn = (wid >> 1) * 16;
    float acc[3][2][2][4] = {};
    for (int k0 = 0; k0 < H_; k0 += BK) {
        split_store(sAh, sAl, ldrawG(g_xhat, H_, k0, m0, g_rows));
        split_store(sBh[0], sBl[0], ldraw(Wr, H_, H_, k0, n0));
        split_store(sBh[1], sBl[1], ldraw(Wz, H_, H_, k0, n0));
        split_store(sBh[2], sBl[2], ldraw(Wh, H_, H_, k0, n0));
        __syncthreads();
#pragma unroll
        for (int w = 0; w < 3; w++)
            mma_tile(acc[w], sAh, sAl, sBh[w], sBl[w], wm, wn, g, tg);
        __syncthreads();
    }
    float* outs[3] = {g_xr, g_xz, g_xh};
#pragma unroll
    for (int w = 0; w < 3; w++)
#pragma unroll
        for (int mt = 0; mt < 2; mt++)
#pragma unroll
            for (int nt = 0; nt < 2; nt++) {
                int r = m0 + wm + mt * 16 + g;
                int c = n0 + wn + nt * 8 + 2 * tg;
                outs[w][(long)r * H_ + c]           = acc[w][mt][nt][0];
                outs[w][(long)r * H_ + c + 1]       = acc[w][mt][nt][1];
                outs[w][(long)(r + 8) * H_ + c]     = acc[w][mt][nt][2];
                outs[w][(long)(r + 8) * H_ + c + 1] = acc[w][mt][nt][3];
            }
}

// ================= fp32 tile slabs =================
__device__ __forceinline__ void sl44(float ac[4][4], const float (*sA)[ST],
                                     const float (*sB)[ST], int ty, int tx) {
#pragma unroll
    for (int k = 0; k < BK; k++) {
        float a[4], b[4];
        *(float4*)a = *(const float4*)&sA[k][ty * 4];
        *(float4*)b = *(const float4*)&sB[k][tx * 4];
#pragma unroll
        for (int i = 0; i < 4; i++)
#pragma unroll
            for (int j = 0; j < 4; j++) ac[i][j] = fmaf(a[i], b[j], ac[i][j]);
    }
}
__device__ __forceinline__ void sl24d(float aR[2][4], float aZ[2][4],
                                      const float (*sA)[SAT], const float (*sB1)[ST],
                                      const float (*sB2)[ST], int ty, int tx) {
#pragma unroll
    for (int k = 0; k < BK; k++) {
        float2 a = *(const float2*)&sA[k][ty * 2];
        float b1[4], b2[4];
        *(float4*)b1 = *(const float4*)&sB1[k][tx * 4];
        *(float4*)b2 = *(const float4*)&sB2[k][tx * 4];
#pragma unroll
        for (int j = 0; j < 4; j++) {
            aR[0][j] = fmaf(a.x, b1[j], aR[0][j]);
            aR[1][j] = fmaf(a.y, b1[j], aR[1][j]);
            aZ[0][j] = fmaf(a.x, b2[j], aZ[0][j]);
            aZ[1][j] = fmaf(a.y, b2[j], aZ[1][j]);
        }
    }
}
__device__ __forceinline__ void sl24(float ac[2][4], const float (*sA)[SAT],
                                     const float (*sB)[ST], int ty, int tx) {
#pragma unroll
    for (int k = 0; k < BK; k++) {
        float2 a = *(const float2*)&sA[k][ty * 2];
        float b[4];
        *(float4*)b = *(const float4*)&sB[k][tx * 4];
#pragma unroll
        for (int j = 0; j < 4; j++) {
            ac[0][j] = fmaf(a.x, b[j], ac[0][j]);
            ac[1][j] = fmaf(a.y, b[j], ac[1][j]);
        }
    }
}

// ---- hs partials (fp32): A = packed adjP (coalesced), split-K = 4 ----------
// Zero-padded A rows make every slab full; extra fmaf(0,b,acc)=acc terms are
// bitwise-neutral -> results identical to the gathered version.
__global__ __launch_bounds__(256) void mm_hs(int lvl) {
    int o0 = g_off[lvl], o1 = g_off[lvl + 1];
    int M = o1 - o0;
    int Ktot = N_ - o1;
    int Kpad = (Ktot + 63) & ~63;
    int m0 = blockIdx.y * 64;
    if (m0 >= M) return;
    int n0 = blockIdx.x * 64;
    int kchunk = Kpad >> 2;
    int kbase = blockIdx.z * kchunk;
    int nsl = kchunk >> 4;

    int ty = threadIdx.x >> 4, tx = threadIdx.x & 15;
    float ac[4][4] = {};
    __shared__ float sA[2][BK][ST], sB[2][BK][ST];
    int alr = threadIdx.x >> 2;
    int alc = (threadIdx.x & 3) << 2;
    int gm = m0 + alr;
    bool av = gm < M;
    long abase = (long)gm * Kpad;
    int bkk = threadIdx.x >> 4;
    int bc  = (threadIdx.x & 15) << 2;
    float4 va, vb;
    {
        va = av ? *(const float4*)(g_xhat + abase + kbase + alc)
                : make_float4(0.f, 0.f, 0.f, 0.f);
        int kb = kbase + bkk;
        vb = (kb < Ktot) ? *(const float4*)(g_hc + (long)(o1 + kb) * H_ + n0 + bc)
                         : make_float4(0.f, 0.f, 0.f, 0.f);
    }
    sA[0][alc + 0][alr] = va.x; sA[0][alc + 1][alr] = va.y;
    sA[0][alc + 2][alr] = va.z; sA[0][alc + 3][alr] = va.w;
    *(float4*)&sB[0][bkk][bc] = vb;
    __syncthreads();
    int cur = 0;
    for (int sl = 0; sl < nsl; sl++) {
        if (sl + 1 < nsl) {
            int k0 = kbase + (sl + 1) * BK;
            va = av ? *(const float4*)(g_xhat + abase + k0 + alc)
                    : make_float4(0.f, 0.f, 0.f, 0.f);
            int kb = k0 + bkk;
            vb = (kb < Ktot) ? *(const float4*)(g_hc + (long)(o1 + kb) * H_ + n0 + bc)
                             : make_float4(0.f, 0.f, 0.f, 0.f);
        }
        sl44(ac, sA[cur], sB[cur], ty, tx);
        if (sl + 1 < nsl) {
            sA[1 - cur][alc + 0][alr] = va.x; sA[1 - cur][alc + 1][alr] = va.y;
            sA[1 - cur][alc + 2][alr] = va.z; sA[1 - cur][alc + 3][alr] = va.w;
            *(float4*)&sB[1 - cur][bkk][bc] = vb;
        }
        __syncthreads();
        cur ^= 1;
    }
    float* P = g_rhs + (long)blockIdx.z * CHUNK;
#pragma unroll
    for (int i = 0; i < 4; i++) {
        int m = m0 + ty * 4 + i;
        if (m >= M) continue;
        *(float4*)&P[(long)m * H_ + n0 + tx * 4] = *(float4*)&ac[i][0];
    }
}
__global__ void reduce_hs_k(int lvl) {
    int M = g_off[lvl + 1] - g_off[lvl];
    long idx = (long)blockIdx.x * 256 + threadIdx.x;
    int m = (int)(idx >> 9);
    if (m >= M) return;
    g_hs[idx] = g_rhs[idx] + g_rhs[idx + CHUNK] +
                g_rhs[idx + 2L * CHUNK] + g_rhs[idx + 3L * CHUNK];
}

// ---------------- r & z gates: fp32, BM=32, K=512 (round-13 proven) ----------
__global__ __launch_bounds__(256) void mm_rz(const float* __restrict__ Ur,
                                             const float* __restrict__ Uz, int lvl) {
    int o0 = g_off[lvl];
    int M = g_off[lvl + 1] - o0;
    int m0 = blockIdx.y * 32;
    if (m0 >= M) return;
    int n0 = blockIdx.x * 64;
    __shared__ float sA[2][BK][SAT], sB1[2][BK][ST], sB2[2][BK][ST];
    int alr = threadIdx.x >> 3, alc = (threadIdx.x & 7) << 1;
    int blr = threadIdx.x >> 2, blc = (threadIdx.x & 3) << 2;
    int ty = threadIdx.x >> 4, tx = threadIdx.x & 15;
    float aR[2][4] = {}, aZ[2][4] = {};
    const int nsl = H_ / BK;
    float2 va; float4 v1, v2;
    va = *(const float2*)(g_hs + (long)(m0 + alr) * H_ + alc);
    v1 = *(const float4*)(Ur + (long)(n0 + blr) * H_ + blc);
    v2 = *(const float4*)(Uz + (long)(n0 + blr) * H_ + blc);
    sA[0][alc][alr] = va.x; sA[0][alc + 1][alr] = va.y;
    sB1[0][blc + 0][blr] = v1.x; sB1[0][blc + 1][blr] = v1.y;
    sB1[0][blc + 2][blr] = v1.z; sB1[0][blc + 3][blr] = v1.w;
    sB2[0][blc + 0][blr] = v2.x; sB2[0][blc + 1][blr] = v2.y;
    sB2[0][blc + 2][blr] = v2.z; sB2[0][blc + 3][blr] = v2.w;
    __syncthreads();
    int cur = 0;
    for (int sl = 0; sl < nsl; sl++) {
        if (sl + 1 < nsl) {
            int k0 = (sl + 1) * BK;
            va = *(const float2*)(g_hs + (long)(m0 + alr) * H_ + k0 + alc);
            v1 = *(const float4*)(Ur + (long)(n0 + blr) * H_ + k0 + blc);
            v2 = *(const float4*)(Uz + (long)(n0 + blr) * H_ + k0 + blc);
        }
        sl24d(aR, aZ, sA[cur], sB1[cur], sB2[cur], ty, tx);
        if (sl + 1 < nsl) {
            sA[1 - cur][alc][alr] = va.x; sA[1 - cur][alc + 1][alr] = va.y;
            sB1[1 - cur][blc + 0][blr] = v1.x; sB1[1 - cur][blc + 1][blr] = v1.y;
            sB1[1 - cur][blc + 2][blr] = v1.z; sB1[1 - cur][blc + 3][blr] = v1.w;
            sB2[1 - cur][blc + 0][blr] = v2.x; sB2[1 - cur][blc + 1][blr] = v2.y;
            sB2[1 - cur][blc + 2][blr] = v2.z; sB2[1 - cur][blc + 3][blr] = v2.w;
        }
        __syncthreads();
        cur ^= 1;
    }
#pragma unroll
    for (int i = 0; i < 2; i++) {
        int m = m0 + ty * 2 + i;
        if (m >= M) continue;
        long cr = (long)(o0 + m) * H_;
        long lm = (long)m * H_;
#pragma unroll
        for (int j = 0; j < 4; j++) {
            int n = n0 + tx * 4 + j;
            float av = (i == 0) ? aR[0][j] : aR[1][j];
            float zv = (i == 0) ? aZ[0][j] : aZ[1][j];
            float r = sigm_(g_xr[cr + n] + av);
            float z = sigm_(g_xz[cr + n] + zv);
            g_rhs[lm + n] = g_hs[lm + n] * r;
            g_rhs[CHUNK + lm + n] = z;
        }
    }
}

// ---------------- h-tilde + GRU combine: fp32, BM=32, K=512 ------------------
__global__ __launch_bounds__(256) void mm_h(const float* __restrict__ Uh, int lvl) {
    int o0 = g_off[lvl];
    int M = g_off[lvl + 1] - o0;
    int m0 = blockIdx.y * 32;
    if (m0 >= M) return;
    int n0 = blockIdx.x * 64;
    __shared__ float sA[2][BK][SAT], sB[2][BK][ST];
    int alr = threadIdx.x >> 3, alc = (threadIdx.x & 7) << 1;
    int blr = threadIdx.x >> 2, blc = (threadIdx.x & 3) << 2;
    int ty = threadIdx.x >> 4, tx = threadIdx.x & 15;
    float ac[2][4] = {};
    const int nsl = H_ / BK;
    float2 va; float4 vb;
    va = *(const float2*)(g_rhs + (long)(m0 + alr) * H_ + alc);
    vb = *(const float4*)(Uh + (long)(n0 + blr) * H_ + blc);
    sA[0][alc][alr] = va.x; sA[0][alc + 1][alr] = va.y;
    sB[0][blc + 0][blr] = vb.x; sB[0][blc + 1][blr] = vb.y;
    sB[0][blc + 2][blr] = vb.z; sB[0][blc + 3][blr] = vb.w;
    __syncthreads();
    int cur = 0;
    for (int sl = 0; sl < nsl; sl++) {
        if (sl + 1 < nsl) {
            int k0 = (sl + 1) * BK;
            va = *(const float2*)(g_rhs + (long)(m0 + alr) * H_ + k0 + alc);
            vb = *(const float4*)(Uh + (long)(n0 + blr) * H_ + k0 + blc);
        }
        sl24(ac, sA[cur], sB[cur], ty, tx);
        if (sl + 1 < nsl) {
            sA[1 - cur][alc][alr] = va.x; sA[1 - cur][alc + 1][alr] = va.y;
            sB[1 - cur][blc + 0][blr] = vb.x; sB[1 - cur][blc + 1][blr] = vb.y;
            sB[1 - cur][blc + 2][blr] = vb.z; sB[1 - cur][blc + 3][blr] = vb.w;
        }
        __syncthreads();
        cur ^= 1;
    }
#pragma unroll
    for (int i = 0; i < 2; i++) {
        int m = m0 + ty * 2 + i;
        if (m >= M) continue;
        long cr = (long)(o0 + m) * H_;
        long lm = (long)m * H_;
#pragma unroll
        for (int j = 0; j < 4; j++) {
            int n = n0 + tx * 4 + j;
            float av = (i == 0) ? ac[0][j] : ac[1][j];
            float hh = tanhf(g_xh[cr + n] + av);
            float z  = g_rhs[CHUNK + lm + n];
            float hs = g_hs[lm + n];
            g_hc[cr + n] = (1.f - z) * hs + z * hh;
        }
    }
}

// ---------------- decoder (compact -> original) ----------------
__global__ void decoder_k(const float* __restrict__ dw,
                          const float* __restrict__ db,
                          float* __restrict__ out) {
    int c = blockIdx.x;
    int tid = threadIdx.x;
    const float* hr = g_hc + (long)c * H_;
    float a0 = 0.f, a1 = 0.f, a2 = 0.f, a3 = 0.f;
    for (int k = tid; k < H_; k += 128) {
        float hv = hr[k];
        a0 = fmaf(hv, dw[0 * H_ + k], a0);
        a1 = fmaf(hv, dw[1 * H_ + k], a1);
        a2 = fmaf(hv, dw[2 * H_ + k], a2);
        a3 = fmaf(hv, dw[3 * H_ + k], a3);
    }
#pragma unroll
    for (int o = 16; o > 0; o >>= 1) {
        a0 += __shfl_down_sync(0xFFFFFFFFu, a0, o);
        a1 += __shfl_down_sync(0xFFFFFFFFu, a1, o);
        a2 += __shfl_down_sync(0xFFFFFFFFu, a2, o);
        a3 += __shfl_down_sync(0xFFFFFFFFu, a3, o);
    }
    __shared__ float s[4][4];
    int w = tid >> 5, l = tid & 31;
    if (l == 0) { s[w][0] = a0; s[w][1] = a1; s[w][2] = a2; s[w][3] = a3; }
    __syncthreads();
    if (tid < C_) {
        int orig = g_rows[c];
        out[(long)orig * C_ + tid] = s[0][tid] + s[1][tid] + s[2][tid] + s[3][tid] + db[tid];
    }
}

// ---------------- static-init preload ----------------
namespace {
struct Preload {
    Preload() {
        cudaSetDevice(0);
        void* p = nullptr;
        cudaGetSymbolAddress(&p, g_hc);
        cudaFuncAttributes at;
        cudaFuncGetAttributes(&at, lvl_init_k);
        cudaFuncGetAttributes(&at, lvl_hist_k);
        cudaFuncGetAttributes(&at, lvl_scan_k);
        cudaFuncGetAttributes(&at, lvl_rank_k);
        cudaFuncGetAttributes(&at, lvl7_k);
        cudaFuncGetAttributes(&at, pack_adj_k);
        cudaFuncGetAttributes(&at, mm_xhat);
        cudaFuncGetAttributes(&at, mm_xw);
        cudaFuncGetAttributes(&at, mm_hs);
        cudaFuncGetAttributes(&at, reduce_hs_k);
        cudaFuncGetAttributes(&at, mm_rz);
        cudaFuncGetAttributes(&at, mm_h);
        cudaFuncGetAttributes(&at, decoder_k);
        lvl_init_k<<<1, 32>>>();
        lvl_scan_k<<<1, 32>>>();
        cudaDeviceSynchronize();
        cudaGetLastError();
    }
};
Preload preload_;
}

// ---------------- launch ----------------
extern "C" void kernel_launch(void* const* d_in, const int* in_sizes, int n_in,
                              void* d_out, int out_size) {
    const float* x     = (const float*)d_in[0];
    const float* adj   = (const float*)d_in[1];
    const int*   level = (const int*)  d_in[2];
    const float* E_w   = (const float*)d_in[3];
    const float* Wr    = (const float*)d_in[4];
    const float* Wz    = (const float*)d_in[5];
    const float* Ur    = (const float*)d_in[6];
    const float* Uz    = (const float*)d_in[7];
    const float* Wh    = (const float*)d_in[8];
    const float* Uh    = (const float*)d_in[9];
    const float* dec_w = (const float*)d_in[10];
    const float* dec_b = (const float*)d_in[11];
    float* out = (float*)d_out;
    (void)in_sizes; (void)n_in; (void)out_size;

    lvl_init_k<<<1, 32>>>();
    lvl_hist_k<<<(N_ + 255) / 256, 256>>>(level);
    lvl_scan_k<<<1, 32>>>();
    lvl_rank_k<<<N_ / 256, 256>>>(level);

    mm_xhat<<<dim3(H_ / 64, N_ / 64), 256>>>(x, E_w);
    mm_xw<<<dim3(H_ / 64, N_ / 64), 256>>>(Wr, Wz, Wh);
    // g_xhat is dead from here on -> reused as adjP by pack_adj_k / mm_hs.

    const int RB = CHUNK / 256;
    dim3 gGate(H_ / 64, 32);   // BM=32, covers M <= 1024
    for (int j = L_ - 1; j >= 0; j--) {
        if (j == L_ - 1) {
            lvl7_k<<<RB, 256>>>();   // closed form (bitwise-exact)
        } else {
            pack_adj_k<<<2048, 256>>>(adj, j);
            mm_hs<<<dim3(8, 16, 4), 256>>>(j);
            reduce_hs_k<<<RB, 256>>>(j);
            mm_rz<<<gGate, 256>>>(Ur, Uz, j);
            mm_h<<<gGate, 256>>>(Uh, j);
        }
    }

    decoder_k<<<N_, 128>>>(dec_w, dec_b, out);
}